// round 3
// baseline (speedup 1.0000x reference)
#include <cuda_runtime.h>
#include <math.h>

#define NN 50000
#define EE 1200000
#define GG 256
#define NBLK 196   // ceil(NN/256)

typedef unsigned long long ull;

// ---------------- f32x2 packed helpers (FFMA2 path) --------------------------
__device__ __forceinline__ ull pk2(float lo, float hi) {
    ull r;
    asm("mov.b64 %0, {%1, %2};" : "=l"(r) : "r"(__float_as_uint(lo)), "r"(__float_as_uint(hi)));
    return r;
}
__device__ __forceinline__ void upk2(ull v, float& lo, float& hi) {
    unsigned a, b;
    asm("mov.b64 {%0, %1}, %2;" : "=r"(a), "=r"(b) : "l"(v));
    lo = __uint_as_float(a);
    hi = __uint_as_float(b);
}
__device__ __forceinline__ void fma2(ull& d, ull a, ull b) {
    asm("fma.rn.f32x2 %0, %1, %2, %0;" : "+l"(d) : "l"(a), "l"(b));
}

// ---------------- scratch ----------------------------------------------------
__device__ float g_hx[NN * 64];      // (x @ conv1_W) * dinv[n]
__device__ float g_h[NN * 64];       // running node features
__device__ float g_u[NN * 64];       // LN+PReLU output per layer
__device__ float g_agg[NN * 64];     // GEN aggregation output
__device__ float g_xcat[NN * 256];   // JK concat buffer
__device__ int   g_hist[NN];
__device__ int   g_rowptr[NN + 1];   // consumed by scatter: ends as row-ENDS
__device__ int   g_colsrc[EE];
__device__ float g_dinv[NN];
__device__ int   g_bsum[NBLK];
__device__ int   g_boff[NBLK];
__device__ int   g_gstart[GG + 1];

// ---------------- init ------------------------------------------------------
__global__ void k_init() {
    int i = blockIdx.x * blockDim.x + threadIdx.x;
    if (i < NN) g_hist[i] = 0;
}

// ---------------- CSR build -------------------------------------------------
__global__ void k_hist(const int* __restrict__ dst) {
    int i = blockIdx.x * blockDim.x + threadIdx.x;
    if (i < EE) atomicAdd(&g_hist[dst[i]], 1);
}

__device__ __forceinline__ int wscan_incl(int x) {
    int lane = threadIdx.x & 31;
#pragma unroll
    for (int o = 1; o < 32; o <<= 1) {
        int y = __shfl_up_sync(0xffffffffu, x, o);
        if (lane >= o) x += y;
    }
    return x;
}

__global__ void k_part() {
    __shared__ int ws[8];
    int tid = threadIdx.x;
    int i = blockIdx.x * 256 + tid;
    int v = (i < NN) ? g_hist[i] : 0;
    int incl = wscan_incl(v);
    if ((tid & 31) == 31) ws[tid >> 5] = incl;
    __syncthreads();
    if (tid == 0) {
        int s = 0;
#pragma unroll
        for (int w = 0; w < 8; w++) s += ws[w];
        g_bsum[blockIdx.x] = s;
    }
}

__global__ void k_scan2() {
    __shared__ int ws[8];
    int tid = threadIdx.x;
    int lane = tid & 31, w = tid >> 5;
    int v = (tid < NBLK) ? g_bsum[tid] : 0;
    int incl = wscan_incl(v);
    if (lane == 31) ws[w] = incl;
    __syncthreads();
    if (tid < 8) {
        int b = ws[tid];
#pragma unroll
        for (int o = 1; o < 8; o <<= 1) {
            int y = __shfl_up_sync(0xffu, b, o);
            if (tid >= o) b += y;
        }
        ws[tid] = b;
    }
    __syncthreads();
    int base = (w > 0) ? ws[w - 1] : 0;
    if (tid < NBLK) g_boff[tid] = base + incl - v;
    if (tid == 0) g_rowptr[NN] = EE;
}

__global__ void k_scan3() {
    __shared__ int ws[8];
    int tid = threadIdx.x;
    int lane = tid & 31, w = tid >> 5;
    int i = blockIdx.x * 256 + tid;
    int v = (i < NN) ? g_hist[i] : 0;
    int incl = wscan_incl(v);
    if (lane == 31) ws[w] = incl;
    __syncthreads();
    if (tid < 8) {
        int b = ws[tid];
#pragma unroll
        for (int o = 1; o < 8; o <<= 1) {
            int y = __shfl_up_sync(0xffu, b, o);
            if (tid >= o) b += y;
        }
        ws[tid] = b;
    }
    __syncthreads();
    int base = (w > 0) ? ws[w - 1] : 0;
    if (i < NN) {
        g_rowptr[i] = g_boff[blockIdx.x] + base + incl - v;
        g_dinv[i] = rsqrtf((float)(v + 1));
    }
}

// scatter consumes rowptr: afterwards g_rowptr[n] == original rowptr[n+1]
__global__ void k_scatter(const int* __restrict__ src, const int* __restrict__ dst) {
    int i = blockIdx.x * blockDim.x + threadIdx.x;
    if (i < EE) {
        int d = dst[i];
        int pos = atomicAdd(&g_rowptr[d], 1);
        g_colsrc[pos] = src[i];
    }
}

// graph boundaries from sorted batch_idx
__global__ void k_gstart(const int* __restrict__ batch) {
    int n = blockIdx.x * blockDim.x + threadIdx.x;
    if (n >= NN) return;
    int b = batch[n];
    int prev = (n == 0) ? -1 : batch[n - 1];
    for (int g = prev + 1; g <= b; g++) g_gstart[g] = n;
    if (n == NN - 1) {
        for (int g = b + 1; g <= GG; g++) g_gstart[g] = NN;
    }
}

// ---------------- x @ conv1_W, pre-scaled by dinv[n] -------------------------
__global__ void k_hx(const float* __restrict__ x, const float* __restrict__ W) {
    int idx = blockIdx.x * blockDim.x + threadIdx.x;
    if (idx >= NN * 64) return;
    int n = idx >> 6, c = idx & 63;
    float a = 0.f;
#pragma unroll
    for (int f = 0; f < 5; f++) a += x[n * 5 + f] * W[f * 64 + c];
    g_hx[idx] = a * g_dinv[n];
}

// ---------------- GCNConv aggregate + BN + ReLU ------------------------------
__global__ void k_gcn(const float* __restrict__ cb, const float* __restrict__ bg,
                      const float* __restrict__ bb) {
    int tid = threadIdx.x;
    int n = blockIdx.x * 4 + (tid >> 6);
    int c = tid & 63;
    if (n >= NN) return;
    float acc = 0.f;
    int b = (n == 0) ? 0 : g_rowptr[n - 1];
    int e = g_rowptr[n];
    int i = b;
    for (; i + 4 <= e; i += 4) {
        int s0 = g_colsrc[i], s1 = g_colsrc[i + 1];
        int s2 = g_colsrc[i + 2], s3 = g_colsrc[i + 3];
        float a0 = g_hx[s0 * 64 + c];
        float a1 = g_hx[s1 * 64 + c];
        float a2 = g_hx[s2 * 64 + c];
        float a3 = g_hx[s3 * 64 + c];
        acc += (a0 + a1) + (a2 + a3);
    }
    for (; i < e; i++) acc += g_hx[g_colsrc[i] * 64 + c];
    acc = (acc + g_hx[n * 64 + c]) * g_dinv[n] + cb[c];
    const float BNS = rsqrtf(1.f + 1e-5f);
    acc = acc * (bg[c] * BNS) + bb[c];
    acc = fmaxf(acc, 0.f);
    g_h[n * 64 + c] = acc;
    g_xcat[n * 256 + c] = acc;
}

// ---------------- LayerNorm + PReLU ------------------------------------------
__global__ void k_ln(const float* __restrict__ g, const float* __restrict__ b,
                     const float* __restrict__ a) {
    int tid = threadIdx.x;
    int n = blockIdx.x * 8 + (tid >> 5);
    int l = tid & 31;
    if (n >= NN) return;
    float v0 = g_h[n * 64 + l];
    float v1 = g_h[n * 64 + l + 32];
    float s = v0 + v1;
    float q = v0 * v0 + v1 * v1;
#pragma unroll
    for (int off = 16; off > 0; off >>= 1) {
        s += __shfl_xor_sync(0xffffffffu, s, off);
        q += __shfl_xor_sync(0xffffffffu, q, off);
    }
    float mu = s * (1.f / 64.f);
    float var = q * (1.f / 64.f) - mu * mu;
    float rs = rsqrtf(var + 1e-5f);
    float y0 = (v0 - mu) * rs * g[l] + b[l];
    y0 = (y0 >= 0.f) ? y0 : a[l] * y0;
    g_u[n * 64 + l] = y0;
    float y1 = (v1 - mu) * rs * g[l + 32] + b[l + 32];
    y1 = (y1 >= 0.f) ? y1 : a[l + 32] * y1;
    g_u[n * 64 + l + 32] = y1;
}

// ---------------- GENConv softmax aggregation (no-max, unrolled) -------------
__global__ void k_gen(const float* __restrict__ gen_t, int layer) {
    int tid = threadIdx.x;
    int n = blockIdx.x * 4 + (tid >> 6);
    int c = tid & 63;
    if (n >= NN) return;
    float t = __ldg(&gen_t[layer]);
    int b = (n == 0) ? 0 : g_rowptr[n - 1];
    int e = g_rowptr[n];
    float s = 0.f, acc = 0.f;
    int i = b;
    for (; i + 4 <= e; i += 4) {
        int s0 = g_colsrc[i], s1 = g_colsrc[i + 1];
        int s2 = g_colsrc[i + 2], s3 = g_colsrc[i + 3];
        float v0 = fmaxf(g_u[s0 * 64 + c], 0.f) + 1e-7f;
        float v1 = fmaxf(g_u[s1 * 64 + c], 0.f) + 1e-7f;
        float v2 = fmaxf(g_u[s2 * 64 + c], 0.f) + 1e-7f;
        float v3 = fmaxf(g_u[s3 * 64 + c], 0.f) + 1e-7f;
        float e0 = __expf(v0 * t);
        float e1 = __expf(v1 * t);
        float e2 = __expf(v2 * t);
        float e3 = __expf(v3 * t);
        s += (e0 + e1) + (e2 + e3);
        acc += (v0 * e0 + v1 * e1) + (v2 * e2 + v3 * e3);
    }
    for (; i < e; i++) {
        float v = fmaxf(g_u[g_colsrc[i] * 64 + c], 0.f) + 1e-7f;
        float ex = __expf(v * t);
        s += ex;
        acc += v * ex;
    }
    float u = g_u[n * 64 + c];
    g_agg[n * 64 + c] = ((e > b) ? (acc / s) : 0.f) + u;
}

// ---------------- fused MLP with f32x2 packed FMAs ---------------------------
// Tiles: aS_T[k=64][node=64] stride 66, z1T[k=128][node=64] stride 66.
// f32x2 halves = (node j, node j+1); weights duplicated per pack.
#define TSTR 66
__global__ void k_mlpf(const float* __restrict__ W1, const float* __restrict__ b1,
                       const float* __restrict__ bng, const float* __restrict__ bnb,
                       const float* __restrict__ W2, const float* __restrict__ b2,
                       int layer) {
    extern __shared__ float dyn[];
    float* W1s  = dyn;                  // 8192
    float* aS_T = dyn + 8192;           // 66*64 = 4224
    float* z1T  = dyn + 8192 + 4224;    // 66*128 = 8448
    int tid = threadIdx.x;
    int n0 = blockIdx.x * 64;
    for (int i = tid; i < 8192; i += 256) W1s[i] = W1[i];
    for (int i = tid; i < 4096; i += 256) {
        int j = i >> 6, k = i & 63;
        int n = n0 + j;
        aS_T[k * TSTR + j] = (n < NN) ? g_agg[n * 64 + k] : 0.f;
    }
    __syncthreads();
    int jt = tid >> 5;        // node group (8 nodes)
    int ot = tid & 31;
    int j0 = jt * 8;

    // ---- stage 1: 64 -> 128, outputs o = ot + 32q ----
    ull acc[4][4];            // [node-pair p][q]
#pragma unroll
    for (int p = 0; p < 4; p++)
#pragma unroll
        for (int q = 0; q < 4; q++) acc[p][q] = 0ull;

    for (int k = 0; k < 64; k++) {
        const float* wr = &W1s[k * 128 + ot];
        ull W0 = pk2(wr[0], wr[0]);
        ull Wq1 = pk2(wr[32], wr[32]);
        ull Wq2 = pk2(wr[64], wr[64]);
        ull Wq3 = pk2(wr[96], wr[96]);
        const float* ar = &aS_T[k * TSTR + j0];
#pragma unroll
        for (int p = 0; p < 4; p++) {
            ull A = *reinterpret_cast<const ull*>(ar + 2 * p);
            fma2(acc[p][0], A, W0);
            fma2(acc[p][1], A, Wq1);
            fma2(acc[p][2], A, Wq2);
            fma2(acc[p][3], A, Wq3);
        }
    }
    // BN + ReLU, store transposed pairs
    const float BNS = rsqrtf(1.f + 1e-5f);
#pragma unroll
    for (int q = 0; q < 4; q++) {
        int o = ot + 32 * q;
        float m = __ldg(&bng[o]) * BNS;
        float c = (__ldg(&b1[o])) * m + __ldg(&bnb[o]);
        float* zr = &z1T[o * TSTR + j0];
#pragma unroll
        for (int p = 0; p < 4; p++) {
            float v0, v1;
            upk2(acc[p][q], v0, v1);
            v0 = fmaxf(v0 * m + c, 0.f);
            v1 = fmaxf(v1 * m + c, 0.f);
            *reinterpret_cast<ull*>(zr + 2 * p) = pk2(v0, v1);
        }
    }
    __syncwarp();   // each warp reads only its own columns

    // ---- stage 2: 128 -> 64, outputs o = ot + 32q (q<2), W2 via L1 ----
    ull a2[4][2];
#pragma unroll
    for (int p = 0; p < 4; p++) { a2[p][0] = 0ull; a2[p][1] = 0ull; }
#pragma unroll 4
    for (int k = 0; k < 128; k++) {
        float w0 = __ldg(&W2[k * 64 + ot]);
        float w1 = __ldg(&W2[k * 64 + ot + 32]);
        ull W0 = pk2(w0, w0);
        ull Wq1 = pk2(w1, w1);
        const float* zr = &z1T[k * TSTR + j0];
#pragma unroll
        for (int p = 0; p < 4; p++) {
            ull A = *reinterpret_cast<const ull*>(zr + 2 * p);
            fma2(a2[p][0], A, W0);
            fma2(a2[p][1], A, Wq1);
        }
    }
#pragma unroll
    for (int q = 0; q < 2; q++) {
        int o = ot + 32 * q;
        float bb = __ldg(&b2[o]);
#pragma unroll
        for (int p = 0; p < 4; p++) {
            float v0, v1;
            upk2(a2[p][q], v0, v1);
            int na = n0 + j0 + 2 * p;
            int nb = na + 1;
            if (na < NN) {
                float nh = g_h[na * 64 + o] + v0 + bb;
                g_h[na * 64 + o] = nh;
                g_xcat[na * 256 + (layer + 1) * 64 + o] = nh;
            }
            if (nb < NN) {
                float nh = g_h[nb * 64 + o] + v1 + bb;
                g_h[nb * 64 + o] = nh;
                g_xcat[nb * 256 + (layer + 1) * 64 + o] = nh;
            }
        }
    }
}

// ---------------- fused pooling + readout MLP --------------------------------
__global__ void k_poolread(const float* __restrict__ W1, const float* __restrict__ b1,
                           const float* __restrict__ W2, const float* __restrict__ b2,
                           const float* __restrict__ Wo, const float* __restrict__ bo,
                           float* __restrict__ out) {
    __shared__ float p[512];
    __shared__ float q1[128];
    __shared__ float q2[64];
    int g = blockIdx.x;
    int tid = threadIdx.x;   // 256
    int beg = g_gstart[g], end = g_gstart[g + 1];
    float sum = 0.f, mx = -INFINITY;
    for (int n = beg; n < end; n++) {
        float v = g_xcat[n * 256 + tid];
        sum += v;
        mx = fmaxf(mx, v);
    }
    float c = (float)(end - beg);
    p[tid] = sum / fmaxf(c, 1.f);
    p[256 + tid] = (end > beg) ? mx : 0.f;
    __syncthreads();
    if (tid < 128) {
        float a = b1[tid];
        for (int k = 0; k < 512; k++) a += p[k] * W1[k * 128 + tid];
        q1[tid] = fmaxf(a, 0.f);
    }
    __syncthreads();
    if (tid < 64) {
        float a = b2[tid];
        for (int k = 0; k < 128; k++) a += q1[k] * W2[k * 64 + tid];
        q2[tid] = fmaxf(a, 0.f);
    }
    __syncthreads();
    if (tid < 32) {
        float s = q2[tid] * Wo[tid] + q2[tid + 32] * Wo[tid + 32];
#pragma unroll
        for (int off = 16; off > 0; off >>= 1) s += __shfl_xor_sync(0xffffffffu, s, off);
        if (tid == 0) out[g] = s + bo[0];
    }
}

// ---------------- launch -----------------------------------------------------
extern "C" void kernel_launch(void* const* d_in, const int* in_sizes, int n_in,
                              void* d_out, int out_size) {
    const float* x        = (const float*)d_in[0];
    const int*   ei       = (const int*)d_in[1];
    const int*   batch    = (const int*)d_in[2];
    const float* conv1_W  = (const float*)d_in[3];
    const float* conv1_b  = (const float*)d_in[4];
    const float* bn1_g    = (const float*)d_in[5];
    const float* bn1_b    = (const float*)d_in[6];
    const float* ln_g     = (const float*)d_in[7];
    const float* ln_b     = (const float*)d_in[8];
    const float* prelu_a  = (const float*)d_in[9];
    const float* gen_t    = (const float*)d_in[10];
    const float* mlp_W1   = (const float*)d_in[11];
    const float* mlp_b1   = (const float*)d_in[12];
    const float* mlp_bn_g = (const float*)d_in[13];
    const float* mlp_bn_b = (const float*)d_in[14];
    const float* mlp_W2   = (const float*)d_in[15];
    const float* mlp_b2   = (const float*)d_in[16];
    const float* lin1_W   = (const float*)d_in[17];
    const float* lin1_b   = (const float*)d_in[18];
    const float* lin2_W   = (const float*)d_in[19];
    const float* lin2_b   = (const float*)d_in[20];
    const float* out_W    = (const float*)d_in[21];
    const float* out_b    = (const float*)d_in[22];
    float* out = (float*)d_out;

    const int* src = ei;
    const int* dst = ei + EE;

    static int smem_set = 0;
    if (!smem_set) {
        cudaFuncSetAttribute(k_mlpf, cudaFuncAttributeMaxDynamicSharedMemorySize, 90000);
        smem_set = 1;
    }

    k_init<<<NBLK, 256>>>();
    k_hist<<<(EE + 255) / 256, 256>>>(dst);
    k_part<<<NBLK, 256>>>();
    k_scan2<<<1, 256>>>();
    k_scan3<<<NBLK, 256>>>();
    k_scatter<<<(EE + 255) / 256, 256>>>(src, dst);
    k_gstart<<<NBLK, 256>>>(batch);
    k_hx<<<(NN * 64 + 255) / 256, 256>>>(x, conv1_W);
    k_gcn<<<(NN + 3) / 4, 256>>>(conv1_b, bn1_g, bn1_b);

    const int MLP_SMEM = (8192 + 66 * 64 + 66 * 128) * 4;
    for (int i = 0; i < 3; i++) {
        k_ln<<<(NN + 7) / 8, 256>>>(ln_g + i * 64, ln_b + i * 64, prelu_a + i * 64);
        k_gen<<<(NN + 3) / 4, 256>>>(gen_t, i);
        k_mlpf<<<(NN + 63) / 64, 256, MLP_SMEM>>>(mlp_W1 + i * 64 * 128, mlp_b1 + i * 128,
                                                  mlp_bn_g + i * 128, mlp_bn_b + i * 128,
                                                  mlp_W2 + i * 128 * 64, mlp_b2 + i * 64, i);
    }

    k_poolread<<<GG, 256>>>(lin1_W, lin1_b, lin2_W, lin2_b, out_W, out_b, out);
}

// round 5
// speedup vs baseline: 1.1059x; 1.1059x over previous
#include <cuda_runtime.h>
#include <cuda_fp16.h>
#include <math.h>

#define NN 50000
#define EE 1200000
#define GG 256
#define NBLK 196   // ceil(NN/256)

// ---------------- scratch ----------------------------------------------------
__device__ float   g_hx[NN * 64];     // (x @ conv1_W) * dinv[n]  (fp32, self term)
__device__ __half2 g_hx16[NN * 32];   // fp16 copy for gather
__device__ float   g_h[NN * 64];      // running node features
__device__ float   g_u[NN * 64];      // LN+PReLU output (fp32, self term)
__device__ __half2 g_u16[NN * 32];    // fp16 copy for gather
__device__ float   g_agg[NN * 64];    // GEN aggregation output
__device__ float   g_xcat[NN * 256];  // JK concat buffer
__device__ int     g_hist[NN];
__device__ int     g_rowptr[NN + 1];  // consumed by scatter: ends as row-ENDS
__device__ int     g_colsrc[EE];
__device__ float   g_dinv[NN];
__device__ int     g_bsum[NBLK];
__device__ int     g_boff[NBLK];
__device__ int     g_gstart[GG + 1];

// ---------------- init ------------------------------------------------------
__global__ void k_init() {
    int i = blockIdx.x * blockDim.x + threadIdx.x;
    if (i < NN) g_hist[i] = 0;
}

// ---------------- CSR build -------------------------------------------------
__global__ void k_hist(const int* __restrict__ dst) {
    int i = blockIdx.x * blockDim.x + threadIdx.x;
    if (i < EE) atomicAdd(&g_hist[dst[i]], 1);
}

__device__ __forceinline__ int wscan_incl(int x) {
    int lane = threadIdx.x & 31;
#pragma unroll
    for (int o = 1; o < 32; o <<= 1) {
        int y = __shfl_up_sync(0xffffffffu, x, o);
        if (lane >= o) x += y;
    }
    return x;
}

__global__ void k_part() {
    __shared__ int ws[8];
    int tid = threadIdx.x;
    int i = blockIdx.x * 256 + tid;
    int v = (i < NN) ? g_hist[i] : 0;
    int incl = wscan_incl(v);
    if ((tid & 31) == 31) ws[tid >> 5] = incl;
    __syncthreads();
    if (tid == 0) {
        int s = 0;
#pragma unroll
        for (int w = 0; w < 8; w++) s += ws[w];
        g_bsum[blockIdx.x] = s;
    }
}

__global__ void k_scan2() {
    __shared__ int ws[8];
    int tid = threadIdx.x;
    int lane = tid & 31, w = tid >> 5;
    int v = (tid < NBLK) ? g_bsum[tid] : 0;
    int incl = wscan_incl(v);
    if (lane == 31) ws[w] = incl;
    __syncthreads();
    if (tid < 8) {
        int b = ws[tid];
#pragma unroll
        for (int o = 1; o < 8; o <<= 1) {
            int y = __shfl_up_sync(0xffu, b, o);
            if (tid >= o) b += y;
        }
        ws[tid] = b;
    }
    __syncthreads();
    int base = (w > 0) ? ws[w - 1] : 0;
    if (tid < NBLK) g_boff[tid] = base + incl - v;
    if (tid == 0) g_rowptr[NN] = EE;
}

__global__ void k_scan3() {
    __shared__ int ws[8];
    int tid = threadIdx.x;
    int lane = tid & 31, w = tid >> 5;
    int i = blockIdx.x * 256 + tid;
    int v = (i < NN) ? g_hist[i] : 0;
    int incl = wscan_incl(v);
    if (lane == 31) ws[w] = incl;
    __syncthreads();
    if (tid < 8) {
        int b = ws[tid];
#pragma unroll
        for (int o = 1; o < 8; o <<= 1) {
            int y = __shfl_up_sync(0xffu, b, o);
            if (tid >= o) b += y;
        }
        ws[tid] = b;
    }
    __syncthreads();
    int base = (w > 0) ? ws[w - 1] : 0;
    if (i < NN) {
        g_rowptr[i] = g_boff[blockIdx.x] + base + incl - v;
        g_dinv[i] = rsqrtf((float)(v + 1));
    }
}

// scatter consumes rowptr: afterwards g_rowptr[n] == original rowptr[n+1]
__global__ void k_scatter(const int* __restrict__ src, const int* __restrict__ dst) {
    int i = blockIdx.x * blockDim.x + threadIdx.x;
    if (i < EE) {
        int d = dst[i];
        int pos = atomicAdd(&g_rowptr[d], 1);
        g_colsrc[pos] = src[i];
    }
}

// graph boundaries from sorted batch_idx
__global__ void k_gstart(const int* __restrict__ batch) {
    int n = blockIdx.x * blockDim.x + threadIdx.x;
    if (n >= NN) return;
    int b = batch[n];
    int prev = (n == 0) ? -1 : batch[n - 1];
    for (int g = prev + 1; g <= b; g++) g_gstart[g] = n;
    if (n == NN - 1) {
        for (int g = b + 1; g <= GG; g++) g_gstart[g] = NN;
    }
}

// ---------------- x @ conv1_W, pre-scaled by dinv[n]; fp32 + fp16 ------------
__global__ void k_hx(const float* __restrict__ x, const float* __restrict__ W) {
    int idx = blockIdx.x * blockDim.x + threadIdx.x;
    if (idx >= NN * 32) return;
    int n = idx >> 5, p = idx & 31;
    float a0 = 0.f, a1 = 0.f;
#pragma unroll
    for (int f = 0; f < 5; f++) {
        float xv = x[n * 5 + f];
        a0 += xv * W[f * 64 + 2 * p];
        a1 += xv * W[f * 64 + 2 * p + 1];
    }
    float dn = g_dinv[n];
    a0 *= dn;
    a1 *= dn;
    float2 o;
    o.x = a0; o.y = a1;
    *reinterpret_cast<float2*>(&g_hx[n * 64 + 2 * p]) = o;
    g_hx16[n * 32 + p] = __floats2half2_rn(a0, a1);
}

// ---------------- GCNConv aggregate + BN + ReLU (warp per node, fp16) --------
__global__ void k_gcn(const float* __restrict__ cb, const float* __restrict__ bg,
                      const float* __restrict__ bb) {
    int tid = threadIdx.x;
    int n = blockIdx.x * 8 + (tid >> 5);
    int l = tid & 31;
    if (n >= NN) return;
    int b = (n == 0) ? 0 : g_rowptr[n - 1];
    int e = g_rowptr[n];
    float a0 = 0.f, a1 = 0.f;
    int i = b;
    for (; i + 4 <= e; i += 4) {
        int sA = g_colsrc[i], sB = g_colsrc[i + 1];
        int sC = g_colsrc[i + 2], sD = g_colsrc[i + 3];
        float2 fA = __half22float2(g_u16[0]);  // placeholder avoided below
        fA = __half22float2(g_hx16[sA * 32 + l]);
        float2 fB = __half22float2(g_hx16[sB * 32 + l]);
        float2 fC = __half22float2(g_hx16[sC * 32 + l]);
        float2 fD = __half22float2(g_hx16[sD * 32 + l]);
        a0 += (fA.x + fB.x) + (fC.x + fD.x);
        a1 += (fA.y + fB.y) + (fC.y + fD.y);
    }
    for (; i < e; i++) {
        float2 f = __half22float2(g_hx16[g_colsrc[i] * 32 + l]);
        a0 += f.x;
        a1 += f.y;
    }
    float2 hx = *reinterpret_cast<const float2*>(&g_hx[n * 64 + 2 * l]);
    float dn = g_dinv[n];
    const float BNS = rsqrtf(1.f + 1e-5f);
    float v0 = (a0 + hx.x) * dn + cb[2 * l];
    float v1 = (a1 + hx.y) * dn + cb[2 * l + 1];
    v0 = fmaxf(v0 * (bg[2 * l] * BNS) + bb[2 * l], 0.f);
    v1 = fmaxf(v1 * (bg[2 * l + 1] * BNS) + bb[2 * l + 1], 0.f);
    float2 o; o.x = v0; o.y = v1;
    *reinterpret_cast<float2*>(&g_h[n * 64 + 2 * l]) = o;
    *reinterpret_cast<float2*>(&g_xcat[n * 256 + 2 * l]) = o;
}

// ---------------- LayerNorm + PReLU; writes fp32 u + fp16 u ------------------
__global__ void k_ln(const float* __restrict__ g, const float* __restrict__ b,
                     const float* __restrict__ a) {
    int tid = threadIdx.x;
    int n = blockIdx.x * 8 + (tid >> 5);
    int l = tid & 31;
    if (n >= NN) return;
    float2 v = *reinterpret_cast<const float2*>(&g_h[n * 64 + 2 * l]);
    float s = v.x + v.y;
    float q = v.x * v.x + v.y * v.y;
#pragma unroll
    for (int off = 16; off > 0; off >>= 1) {
        s += __shfl_xor_sync(0xffffffffu, s, off);
        q += __shfl_xor_sync(0xffffffffu, q, off);
    }
    float mu = s * (1.f / 64.f);
    float var = q * (1.f / 64.f) - mu * mu;
    float rs = rsqrtf(var + 1e-5f);
    float y0 = (v.x - mu) * rs * g[2 * l] + b[2 * l];
    y0 = (y0 >= 0.f) ? y0 : a[2 * l] * y0;
    float y1 = (v.y - mu) * rs * g[2 * l + 1] + b[2 * l + 1];
    y1 = (y1 >= 0.f) ? y1 : a[2 * l + 1] * y1;
    float2 o; o.x = y0; o.y = y1;
    *reinterpret_cast<float2*>(&g_u[n * 64 + 2 * l]) = o;
    g_u16[n * 32 + l] = __floats2half2_rn(y0, y1);
}

// ---------------- GENConv softmax aggregation (warp per node, fp16) ----------
__global__ void k_gen(const float* __restrict__ gen_t, int layer) {
    int tid = threadIdx.x;
    int n = blockIdx.x * 8 + (tid >> 5);
    int l = tid & 31;
    if (n >= NN) return;
    float t = __ldg(&gen_t[layer]);
    int b = (n == 0) ? 0 : g_rowptr[n - 1];
    int e = g_rowptr[n];
    float s0 = 0.f, s1 = 0.f, ac0 = 0.f, ac1 = 0.f;
    int i = b;
    for (; i + 4 <= e; i += 4) {
        int sA = g_colsrc[i], sB = g_colsrc[i + 1];
        int sC = g_colsrc[i + 2], sD = g_colsrc[i + 3];
        float2 fA = __half22float2(g_u16[sA * 32 + l]);
        float2 fB = __half22float2(g_u16[sB * 32 + l]);
        float2 fC = __half22float2(g_u16[sC * 32 + l]);
        float2 fD = __half22float2(g_u16[sD * 32 + l]);
        float vA0 = fmaxf(fA.x, 0.f) + 1e-7f, vA1 = fmaxf(fA.y, 0.f) + 1e-7f;
        float vB0 = fmaxf(fB.x, 0.f) + 1e-7f, vB1 = fmaxf(fB.y, 0.f) + 1e-7f;
        float vC0 = fmaxf(fC.x, 0.f) + 1e-7f, vC1 = fmaxf(fC.y, 0.f) + 1e-7f;
        float vD0 = fmaxf(fD.x, 0.f) + 1e-7f, vD1 = fmaxf(fD.y, 0.f) + 1e-7f;
        float eA0 = __expf(vA0 * t), eA1 = __expf(vA1 * t);
        float eB0 = __expf(vB0 * t), eB1 = __expf(vB1 * t);
        float eC0 = __expf(vC0 * t), eC1 = __expf(vC1 * t);
        float eD0 = __expf(vD0 * t), eD1 = __expf(vD1 * t);
        s0 += (eA0 + eB0) + (eC0 + eD0);
        s1 += (eA1 + eB1) + (eC1 + eD1);
        ac0 += (vA0 * eA0 + vB0 * eB0) + (vC0 * eC0 + vD0 * eD0);
        ac1 += (vA1 * eA1 + vB1 * eB1) + (vC1 * eC1 + vD1 * eD1);
    }
    for (; i < e; i++) {
        float2 f = __half22float2(g_u16[g_colsrc[i] * 32 + l]);
        float v0 = fmaxf(f.x, 0.f) + 1e-7f;
        float v1 = fmaxf(f.y, 0.f) + 1e-7f;
        float e0 = __expf(v0 * t), e1 = __expf(v1 * t);
        s0 += e0; s1 += e1;
        ac0 += v0 * e0; ac1 += v1 * e1;
    }
    float2 u = *reinterpret_cast<const float2*>(&g_u[n * 64 + 2 * l]);
    float2 o;
    o.x = ((e > b) ? (ac0 / s0) : 0.f) + u.x;
    o.y = ((e > b) ? (ac1 / s1) : 0.f) + u.y;
    *reinterpret_cast<float2*>(&g_agg[n * 64 + 2 * l]) = o;
}

// ---------------- fused MLP (R2 scalar version) ------------------------------
__global__ void k_mlpf(const float* __restrict__ W1, const float* __restrict__ b1,
                       const float* __restrict__ bng, const float* __restrict__ bnb,
                       const float* __restrict__ W2, const float* __restrict__ b2,
                       int layer) {
    extern __shared__ float dyn[];
    float* W1s = dyn;            // 8192 floats
    float* W2s = dyn + 8192;     // 8192
    float* aS  = dyn + 16384;    // 4096
    float* z1S = dyn + 20480;    // 8192
    int tid = threadIdx.x;
    int n0 = blockIdx.x * 64;
    for (int i = tid; i < 8192; i += 256) { W1s[i] = W1[i]; W2s[i] = W2[i]; }
    for (int i = tid; i < 4096; i += 256) {
        int j = i >> 6, k = i & 63;
        int n = n0 + j;
        aS[i] = (n < NN) ? g_agg[n * 64 + k] : 0.f;
    }
    __syncthreads();
    int jt = tid >> 5;
    int ot = tid & 31;
    int j0 = jt * 8;
    float acc[8][4];
#pragma unroll
    for (int jj = 0; jj < 8; jj++)
#pragma unroll
        for (int q = 0; q < 4; q++) acc[jj][q] = 0.f;
    for (int k = 0; k < 64; k++) {
        float w0 = W1s[k * 128 + ot];
        float w1 = W1s[k * 128 + ot + 32];
        float w2 = W1s[k * 128 + ot + 64];
        float w3 = W1s[k * 128 + ot + 96];
#pragma unroll
        for (int jj = 0; jj < 8; jj++) {
            float av = aS[(j0 + jj) * 64 + k];
            acc[jj][0] += av * w0;
            acc[jj][1] += av * w1;
            acc[jj][2] += av * w2;
            acc[jj][3] += av * w3;
        }
    }
    const float BNS = rsqrtf(1.f + 1e-5f);
#pragma unroll
    for (int jj = 0; jj < 8; jj++) {
#pragma unroll
        for (int q = 0; q < 4; q++) {
            int o = ot + 32 * q;
            float v = acc[jj][q] + b1[o];
            v = v * (bng[o] * BNS) + bnb[o];
            z1S[(j0 + jj) * 128 + o] = fmaxf(v, 0.f);
        }
    }
    __syncwarp();
    float a2[8][2];
#pragma unroll
    for (int jj = 0; jj < 8; jj++) { a2[jj][0] = 0.f; a2[jj][1] = 0.f; }
    for (int k = 0; k < 128; k++) {
        float w0 = W2s[k * 64 + ot];
        float w1 = W2s[k * 64 + ot + 32];
#pragma unroll
        for (int jj = 0; jj < 8; jj++) {
            float av = z1S[(j0 + jj) * 128 + k];
            a2[jj][0] += av * w0;
            a2[jj][1] += av * w1;
        }
    }
#pragma unroll
    for (int jj = 0; jj < 8; jj++) {
        int n = n0 + j0 + jj;
        if (n >= NN) continue;
#pragma unroll
        for (int q = 0; q < 2; q++) {
            int o = ot + 32 * q;
            float v = a2[jj][q] + b2[o];
            float nh = g_h[n * 64 + o] + v;
            g_h[n * 64 + o] = nh;
            g_xcat[n * 256 + (layer + 1) * 64 + o] = nh;
        }
    }
}

// ---------------- fused pooling + readout MLP --------------------------------
__global__ void k_poolread(const float* __restrict__ W1, const float* __restrict__ b1,
                           const float* __restrict__ W2, const float* __restrict__ b2,
                           const float* __restrict__ Wo, const float* __restrict__ bo,
                           float* __restrict__ out) {
    __shared__ float p[512];
    __shared__ float q1[128];
    __shared__ float q2[64];
    int g = blockIdx.x;
    int tid = threadIdx.x;   // 256
    int beg = g_gstart[g], end = g_gstart[g + 1];
    float sum = 0.f, mx = -INFINITY;
    for (int n = beg; n < end; n++) {
        float v = g_xcat[n * 256 + tid];
        sum += v;
        mx = fmaxf(mx, v);
    }
    float c = (float)(end - beg);
    p[tid] = sum / fmaxf(c, 1.f);
    p[256 + tid] = (end > beg) ? mx : 0.f;
    __syncthreads();
    if (tid < 128) {
        float a = b1[tid];
        for (int k = 0; k < 512; k++) a += p[k] * W1[k * 128 + tid];
        q1[tid] = fmaxf(a, 0.f);
    }
    __syncthreads();
    if (tid < 64) {
        float a = b2[tid];
        for (int k = 0; k < 128; k++) a += q1[k] * W2[k * 64 + tid];
        q2[tid] = fmaxf(a, 0.f);
    }
    __syncthreads();
    if (tid < 32) {
        float s = q2[tid] * Wo[tid] + q2[tid + 32] * Wo[tid + 32];
#pragma unroll
        for (int off = 16; off > 0; off >>= 1) s += __shfl_xor_sync(0xffffffffu, s, off);
        if (tid == 0) out[g] = s + bo[0];
    }
}

// ---------------- launch -----------------------------------------------------
extern "C" void kernel_launch(void* const* d_in, const int* in_sizes, int n_in,
                              void* d_out, int out_size) {
    const float* x        = (const float*)d_in[0];
    const int*   ei       = (const int*)d_in[1];
    const int*   batch    = (const int*)d_in[2];
    const float* conv1_W  = (const float*)d_in[3];
    const float* conv1_b  = (const float*)d_in[4];
    const float* bn1_g    = (const float*)d_in[5];
    const float* bn1_b    = (const float*)d_in[6];
    const float* ln_g     = (const float*)d_in[7];
    const float* ln_b     = (const float*)d_in[8];
    const float* prelu_a  = (const float*)d_in[9];
    const float* gen_t    = (const float*)d_in[10];
    const float* mlp_W1   = (const float*)d_in[11];
    const float* mlp_b1   = (const float*)d_in[12];
    const float* mlp_bn_g = (const float*)d_in[13];
    const float* mlp_bn_b = (const float*)d_in[14];
    const float* mlp_W2   = (const float*)d_in[15];
    const float* mlp_b2   = (const float*)d_in[16];
    const float* lin1_W   = (const float*)d_in[17];
    const float* lin1_b   = (const float*)d_in[18];
    const float* lin2_W   = (const float*)d_in[19];
    const float* lin2_b   = (const float*)d_in[20];
    const float* out_W    = (const float*)d_in[21];
    const float* out_b    = (const float*)d_in[22];
    float* out = (float*)d_out;

    const int* src = ei;
    const int* dst = ei + EE;

    static int smem_set = 0;
    if (!smem_set) {
        cudaFuncSetAttribute(k_mlpf, cudaFuncAttributeMaxDynamicSharedMemorySize, 114688);
        smem_set = 1;
    }

    k_init<<<NBLK, 256>>>();
    k_hist<<<(EE + 255) / 256, 256>>>(dst);
    k_part<<<NBLK, 256>>>();
    k_scan2<<<1, 256>>>();
    k_scan3<<<NBLK, 256>>>();
    k_scatter<<<(EE + 255) / 256, 256>>>(src, dst);
    k_gstart<<<NBLK, 256>>>(batch);
    k_hx<<<(NN * 32 + 255) / 256, 256>>>(x, conv1_W);
    k_gcn<<<(NN + 7) / 8, 256>>>(conv1_b, bn1_g, bn1_b);

    for (int i = 0; i < 3; i++) {
        k_ln<<<(NN + 7) / 8, 256>>>(ln_g + i * 64, ln_b + i * 64, prelu_a + i * 64);
        k_gen<<<(NN + 7) / 8, 256>>>(gen_t, i);
        k_mlpf<<<(NN + 63) / 64, 256, 114688>>>(mlp_W1 + i * 64 * 128, mlp_b1 + i * 128,
                                                mlp_bn_g + i * 128, mlp_bn_b + i * 128,
                                                mlp_W2 + i * 128 * 64, mlp_b2 + i * 64, i);
    }

    k_poolread<<<GG, 256>>>(lin1_W, lin1_b, lin2_W, lin2_b, out_W, out_b, out);
}

// round 8
// speedup vs baseline: 1.3867x; 1.2539x over previous
#include <cuda_runtime.h>
#include <cuda_fp16.h>
#include <math.h>
#include <stdint.h>

#define NN 50000
#define EE 1200000
#define GG 256
#define NBLK 196   // ceil(NN/256)

// ---------------- scratch ----------------------------------------------------
__device__ float   g_hx[NN * 64];     // (x @ conv1_W) * dinv[n]  (fp32, self term)
__device__ __half2 g_hx16[NN * 32];   // fp16 copy for gather
__device__ float   g_h[NN * 64];      // running node features
__device__ float   g_u[NN * 64];      // LN+PReLU output (fp32, self term)
__device__ __half2 g_u16[NN * 32];    // fp16 copy for gather
__device__ __half2 g_agg16[NN * 32];  // GEN aggregation output (fp16, MLP input)
__device__ float   g_xcat[NN * 256];  // JK concat buffer
__device__ int     g_hist[NN];
__device__ int     g_rowptr[NN + 1];  // consumed by scatter: ends as row-ENDS
__device__ int     g_colsrc[EE];
__device__ float   g_dinv[NN];
__device__ int     g_bsum[NBLK];
__device__ int     g_boff[NBLK];
__device__ int     g_gstart[GG + 1];
__device__ __half  g_W1T[3 * 8192];   // W1^T fp16: [layer][o=128][k=64]
__device__ __half  g_W2T[3 * 8192];   // W2^T fp16: [layer][n=64][k=128]

__device__ __forceinline__ uint32_t smem_u32(const void* p) {
    uint32_t a;
    asm("{ .reg .u64 t; cvta.to.shared.u64 t, %1; cvt.u32.u64 %0, t; }" : "=r"(a) : "l"(p));
    return a;
}

// ---------------- init ------------------------------------------------------
__global__ void k_init() {
    int i = blockIdx.x * blockDim.x + threadIdx.x;
    if (i < NN) g_hist[i] = 0;
}

// ---------------- CSR build -------------------------------------------------
__global__ void k_hist(const int* __restrict__ dst) {
    int i = blockIdx.x * blockDim.x + threadIdx.x;
    if (i < EE) atomicAdd(&g_hist[dst[i]], 1);
}

__device__ __forceinline__ int wscan_incl(int x) {
    int lane = threadIdx.x & 31;
#pragma unroll
    for (int o = 1; o < 32; o <<= 1) {
        int y = __shfl_up_sync(0xffffffffu, x, o);
        if (lane >= o) x += y;
    }
    return x;
}

__global__ void k_part() {
    __shared__ int ws[8];
    int tid = threadIdx.x;
    int i = blockIdx.x * 256 + tid;
    int v = (i < NN) ? g_hist[i] : 0;
    int incl = wscan_incl(v);
    if ((tid & 31) == 31) ws[tid >> 5] = incl;
    __syncthreads();
    if (tid == 0) {
        int s = 0;
#pragma unroll
        for (int w = 0; w < 8; w++) s += ws[w];
        g_bsum[blockIdx.x] = s;
    }
}

__global__ void k_scan2() {
    __shared__ int ws[8];
    int tid = threadIdx.x;
    int lane = tid & 31, w = tid >> 5;
    int v = (tid < NBLK) ? g_bsum[tid] : 0;
    int incl = wscan_incl(v);
    if (lane == 31) ws[w] = incl;
    __syncthreads();
    if (tid < 8) {
        int b = ws[tid];
#pragma unroll
        for (int o = 1; o < 8; o <<= 1) {
            int y = __shfl_up_sync(0xffu, b, o);
            if (tid >= o) b += y;
        }
        ws[tid] = b;
    }
    __syncthreads();
    int base = (w > 0) ? ws[w - 1] : 0;
    if (tid < NBLK) g_boff[tid] = base + incl - v;
    if (tid == 0) g_rowptr[NN] = EE;
}

__global__ void k_scan3() {
    __shared__ int ws[8];
    int tid = threadIdx.x;
    int lane = tid & 31, w = tid >> 5;
    int i = blockIdx.x * 256 + tid;
    int v = (i < NN) ? g_hist[i] : 0;
    int incl = wscan_incl(v);
    if (lane == 31) ws[w] = incl;
    __syncthreads();
    if (tid < 8) {
        int b = ws[tid];
#pragma unroll
        for (int o = 1; o < 8; o <<= 1) {
            int y = __shfl_up_sync(0xffu, b, o);
            if (tid >= o) b += y;
        }
        ws[tid] = b;
    }
    __syncthreads();
    int base = (w > 0) ? ws[w - 1] : 0;
    if (i < NN) {
        g_rowptr[i] = g_boff[blockIdx.x] + base + incl - v;
        g_dinv[i] = rsqrtf((float)(v + 1));
    }
}

// scatter consumes rowptr: afterwards g_rowptr[n] == original rowptr[n+1]
__global__ void k_scatter(const int* __restrict__ src, const int* __restrict__ dst) {
    int i = blockIdx.x * blockDim.x + threadIdx.x;
    if (i < EE) {
        int d = dst[i];
        int pos = atomicAdd(&g_rowptr[d], 1);
        g_colsrc[pos] = src[i];
    }
}

// graph boundaries from sorted batch_idx
__global__ void k_gstart(const int* __restrict__ batch) {
    int n = blockIdx.x * blockDim.x + threadIdx.x;
    if (n >= NN) return;
    int b = batch[n];
    int prev = (n == 0) ? -1 : batch[n - 1];
    for (int g = prev + 1; g <= b; g++) g_gstart[g] = n;
    if (n == NN - 1) {
        for (int g = b + 1; g <= GG; g++) g_gstart[g] = NN;
    }
}

// ---------------- weight prep: fp16 transposed ------------------------------
__global__ void k_wprep(const float* __restrict__ W1, const float* __restrict__ W2) {
    int idx = blockIdx.x * blockDim.x + threadIdx.x;
    if (idx < 3 * 8192) {
        int l = idx >> 13, r = idx & 8191;
        int o = r >> 6, k = r & 63;
        g_W1T[idx] = __float2half(W1[l * 8192 + k * 128 + o]);
    } else if (idx < 6 * 8192) {
        int t = idx - 3 * 8192;
        int l = t >> 13, r = t & 8191;
        int n = r >> 7, k = r & 127;
        g_W2T[t] = __float2half(W2[l * 8192 + k * 64 + n]);
    }
}

// ---------------- x @ conv1_W, pre-scaled by dinv[n]; fp32 + fp16 ------------
__global__ void k_hx(const float* __restrict__ x, const float* __restrict__ W) {
    int idx = blockIdx.x * blockDim.x + threadIdx.x;
    if (idx >= NN * 32) return;
    int n = idx >> 5, p = idx & 31;
    float a0 = 0.f, a1 = 0.f;
#pragma unroll
    for (int f = 0; f < 5; f++) {
        float xv = x[n * 5 + f];
        a0 += xv * W[f * 64 + 2 * p];
        a1 += xv * W[f * 64 + 2 * p + 1];
    }
    float dn = g_dinv[n];
    a0 *= dn;
    a1 *= dn;
    float2 o;
    o.x = a0; o.y = a1;
    *reinterpret_cast<float2*>(&g_hx[n * 64 + 2 * p]) = o;
    g_hx16[n * 32 + p] = __floats2half2_rn(a0, a1);
}

// ---------------- GCNConv aggregate + BN + ReLU (warp per node, fp16) --------
__global__ void k_gcn(const float* __restrict__ cb, const float* __restrict__ bg,
                      const float* __restrict__ bb) {
    int tid = threadIdx.x;
    int n = blockIdx.x * 8 + (tid >> 5);
    int l = tid & 31;
    if (n >= NN) return;
    int b = (n == 0) ? 0 : g_rowptr[n - 1];
    int e = g_rowptr[n];
    float a0 = 0.f, a1 = 0.f;
    int i = b;
    for (; i + 4 <= e; i += 4) {
        int sA = g_colsrc[i], sB = g_colsrc[i + 1];
        int sC = g_colsrc[i + 2], sD = g_colsrc[i + 3];
        float2 fA = __half22float2(g_hx16[sA * 32 + l]);
        float2 fB = __half22float2(g_hx16[sB * 32 + l]);
        float2 fC = __half22float2(g_hx16[sC * 32 + l]);
        float2 fD = __half22float2(g_hx16[sD * 32 + l]);
        a0 += (fA.x + fB.x) + (fC.x + fD.x);
        a1 += (fA.y + fB.y) + (fC.y + fD.y);
    }
    for (; i < e; i++) {
        float2 f = __half22float2(g_hx16[g_colsrc[i] * 32 + l]);
        a0 += f.x;
        a1 += f.y;
    }
    float2 hx = *reinterpret_cast<const float2*>(&g_hx[n * 64 + 2 * l]);
    float dn = g_dinv[n];
    const float BNS = rsqrtf(1.f + 1e-5f);
    float v0 = (a0 + hx.x) * dn + cb[2 * l];
    float v1 = (a1 + hx.y) * dn + cb[2 * l + 1];
    v0 = fmaxf(v0 * (bg[2 * l] * BNS) + bb[2 * l], 0.f);
    v1 = fmaxf(v1 * (bg[2 * l + 1] * BNS) + bb[2 * l + 1], 0.f);
    float2 o; o.x = v0; o.y = v1;
    *reinterpret_cast<float2*>(&g_h[n * 64 + 2 * l]) = o;
    *reinterpret_cast<float2*>(&g_xcat[n * 256 + 2 * l]) = o;
}

// ---------------- LayerNorm + PReLU; writes fp32 u + fp16 u ------------------
__global__ void k_ln(const float* __restrict__ g, const float* __restrict__ b,
                     const float* __restrict__ a) {
    int tid = threadIdx.x;
    int n = blockIdx.x * 8 + (tid >> 5);
    int l = tid & 31;
    if (n >= NN) return;
    float2 v = *reinterpret_cast<const float2*>(&g_h[n * 64 + 2 * l]);
    float s = v.x + v.y;
    float q = v.x * v.x + v.y * v.y;
#pragma unroll
    for (int off = 16; off > 0; off >>= 1) {
        s += __shfl_xor_sync(0xffffffffu, s, off);
        q += __shfl_xor_sync(0xffffffffu, q, off);
    }
    float mu = s * (1.f / 64.f);
    float var = q * (1.f / 64.f) - mu * mu;
    float rs = rsqrtf(var + 1e-5f);
    float y0 = (v.x - mu) * rs * g[2 * l] + b[2 * l];
    y0 = (y0 >= 0.f) ? y0 : a[2 * l] * y0;
    float y1 = (v.y - mu) * rs * g[2 * l + 1] + b[2 * l + 1];
    y1 = (y1 >= 0.f) ? y1 : a[2 * l + 1] * y1;
    float2 o; o.x = y0; o.y = y1;
    *reinterpret_cast<float2*>(&g_u[n * 64 + 2 * l]) = o;
    g_u16[n * 32 + l] = __floats2half2_rn(y0, y1);
}

// ---------------- GENConv softmax aggregation (warp per node, fp16) ----------
__global__ void k_gen(const float* __restrict__ gen_t, int layer) {
    int tid = threadIdx.x;
    int n = blockIdx.x * 8 + (tid >> 5);
    int l = tid & 31;
    if (n >= NN) return;
    float t = __ldg(&gen_t[layer]);
    int b = (n == 0) ? 0 : g_rowptr[n - 1];
    int e = g_rowptr[n];
    float s0 = 0.f, s1 = 0.f, ac0 = 0.f, ac1 = 0.f;
    int i = b;
    for (; i + 4 <= e; i += 4) {
        int sA = g_colsrc[i], sB = g_colsrc[i + 1];
        int sC = g_colsrc[i + 2], sD = g_colsrc[i + 3];
        float2 fA = __half22float2(g_u16[sA * 32 + l]);
        float2 fB = __half22float2(g_u16[sB * 32 + l]);
        float2 fC = __half22float2(g_u16[sC * 32 + l]);
        float2 fD = __half22float2(g_u16[sD * 32 + l]);
        float vA0 = fmaxf(fA.x, 0.f) + 1e-7f, vA1 = fmaxf(fA.y, 0.f) + 1e-7f;
        float vB0 = fmaxf(fB.x, 0.f) + 1e-7f, vB1 = fmaxf(fB.y, 0.f) + 1e-7f;
        float vC0 = fmaxf(fC.x, 0.f) + 1e-7f, vC1 = fmaxf(fC.y, 0.f) + 1e-7f;
        float vD0 = fmaxf(fD.x, 0.f) + 1e-7f, vD1 = fmaxf(fD.y, 0.f) + 1e-7f;
        float eA0 = __expf(vA0 * t), eA1 = __expf(vA1 * t);
        float eB0 = __expf(vB0 * t), eB1 = __expf(vB1 * t);
        float eC0 = __expf(vC0 * t), eC1 = __expf(vC1 * t);
        float eD0 = __expf(vD0 * t), eD1 = __expf(vD1 * t);
        s0 += (eA0 + eB0) + (eC0 + eD0);
        s1 += (eA1 + eB1) + (eC1 + eD1);
        ac0 += (vA0 * eA0 + vB0 * eB0) + (vC0 * eC0 + vD0 * eD0);
        ac1 += (vA1 * eA1 + vB1 * eB1) + (vC1 * eC1 + vD1 * eD1);
    }
    for (; i < e; i++) {
        float2 f = __half22float2(g_u16[g_colsrc[i] * 32 + l]);
        float v0 = fmaxf(f.x, 0.f) + 1e-7f;
        float v1 = fmaxf(f.y, 0.f) + 1e-7f;
        float e0 = __expf(v0 * t), e1 = __expf(v1 * t);
        s0 += e0; s1 += e1;
        ac0 += v0 * e0; ac1 += v1 * e1;
    }
    float2 u = *reinterpret_cast<const float2*>(&g_u[n * 64 + 2 * l]);
    float o0 = ((e > b) ? (ac0 / s0) : 0.f) + u.x;
    float o1 = ((e > b) ? (ac1 / s1) : 0.f) + u.y;
    g_agg16[n * 32 + l] = __floats2half2_rn(o0, o1);
}

// ---------------- HMMA fused MLP ---------------------------------------------
// Block: 128 nodes, 256 threads (8 warps x 16 rows).
// Stage1: D1[128x128] = A[128x64] @ W1T[128x64]^T  (mma.m16n8k16, fp32 acc)
// Stage2: D2[128x64]  = z[128x128] @ W2T[64x128]^T, z stays in registers.
#define STA 72    // halves per A row (144B, 16B-multiple)
#define STW2 136  // halves per W2 row (272B)

__device__ __forceinline__ void ldmx4(uint32_t addr, uint32_t& a0, uint32_t& a1,
                                      uint32_t& a2, uint32_t& a3) {
    asm volatile("ldmatrix.sync.aligned.m8n8.x4.shared.b16 {%0,%1,%2,%3}, [%4];"
                 : "=r"(a0), "=r"(a1), "=r"(a2), "=r"(a3) : "r"(addr));
}
__device__ __forceinline__ void ldmx2(uint32_t addr, uint32_t& b0, uint32_t& b1) {
    asm volatile("ldmatrix.sync.aligned.m8n8.x2.shared.b16 {%0,%1}, [%2];"
                 : "=r"(b0), "=r"(b1) : "r"(addr));
}
__device__ __forceinline__ void mma16816(float* c, const uint32_t* a, const uint32_t* b) {
    asm volatile("mma.sync.aligned.m16n8k16.row.col.f32.f16.f16.f32 "
                 "{%0,%1,%2,%3}, {%4,%5,%6,%7}, {%8,%9}, {%0,%1,%2,%3};"
                 : "+f"(c[0]), "+f"(c[1]), "+f"(c[2]), "+f"(c[3])
                 : "r"(a[0]), "r"(a[1]), "r"(a[2]), "r"(a[3]), "r"(b[0]), "r"(b[1]));
}

__global__ void __launch_bounds__(256)
k_mma(const float* __restrict__ b1, const float* __restrict__ bng,
      const float* __restrict__ bnb, const float* __restrict__ b2, int layer) {
    extern __shared__ char smem[];
    float*  mpar = (float*)smem;              // 128
    float*  apar = mpar + 128;                // 128
    __half* sA   = (__half*)(apar + 128);     // 128*STA
    __half* sW1  = sA + 128 * STA;            // 128*STA
    __half* sW2  = sW1 + 128 * STA;           // 64*STW2
    int tid = threadIdx.x;
    int n0 = blockIdx.x * 128;

    if (tid < 128) {
        const float BNS = rsqrtf(1.f + 1e-5f);
        float m = __ldg(&bng[tid]) * BNS;
        mpar[tid] = m;
        apar[tid] = __ldg(&b1[tid]) * m + __ldg(&bnb[tid]);
    }
    // A tile (zero-pad rows past NN)
    for (int i = tid; i < 128 * 32; i += 256) {
        int r = i >> 5, p = i & 31;
        int n = n0 + r;
        __half2 v = (n < NN) ? g_agg16[n * 32 + p] : __floats2half2_rn(0.f, 0.f);
        *(__half2*)&sA[r * STA + 2 * p] = v;
    }
    const __half* w1p = g_W1T + layer * 8192;
    for (int i = tid; i < 128 * 32; i += 256) {
        int r = i >> 5, p = i & 31;
        *(__half2*)&sW1[r * STA + 2 * p] = *(const __half2*)&w1p[r * 64 + 2 * p];
    }
    const __half* w2p = g_W2T + layer * 8192;
    for (int i = tid; i < 64 * 64; i += 256) {
        int r = i >> 6, p = i & 63;
        *(__half2*)&sW2[r * STW2 + 2 * p] = *(const __half2*)&w2p[r * 128 + 2 * p];
    }
    __syncthreads();

    int wid = tid >> 5, lane = tid & 31;
    int m0 = wid * 16;

    // ---- stage 1 ----
    float c[16][4];
#pragma unroll
    for (int nt = 0; nt < 16; nt++)
#pragma unroll
        for (int q = 0; q < 4; q++) c[nt][q] = 0.f;

    int arow = m0 + (lane & 7) + ((lane >> 3) & 1) * 8;
    int acolbase = (lane >> 4) * 8;
    int brow = (lane & 7);
    int bcolbase = ((lane >> 3) & 1) * 8;
#pragma unroll
    for (int kt = 0; kt < 4; kt++) {
        uint32_t a[4];
        ldmx4(smem_u32(&sA[arow * STA + kt * 16 + acolbase]), a[0], a[1], a[2], a[3]);
#pragma unroll
        for (int nt = 0; nt < 16; nt++) {
            uint32_t b[2];
            ldmx2(smem_u32(&sW1[(nt * 8 + brow) * STA + kt * 16 + bcolbase]), b[0], b[1]);
            mma16816(c[nt], a, b);
        }
    }

    // ---- epilogue 1 (BN+ReLU) -> stage-2 A fragments in registers ----
    int ob = (lane & 3) * 2;
    uint32_t az[8][4];
#pragma unroll
    for (int nt = 0; nt < 16; nt++) {
        int o0 = nt * 8 + ob, o1 = o0 + 1;
        float m0f = mpar[o0], m1f = mpar[o1];
        float a0f = apar[o0], a1f = apar[o1];
        float z0 = fmaxf(c[nt][0] * m0f + a0f, 0.f);
        float z1 = fmaxf(c[nt][1] * m1f + a1f, 0.f);
        float z2 = fmaxf(c[nt][2] * m0f + a0f, 0.f);
        float z3 = fmaxf(c[nt][3] * m1f + a1f, 0.f);
        __half2 p01 = __floats2half2_rn(z0, z1);
        __half2 p23 = __floats2half2_rn(z2, z3);
        az[nt >> 1][(nt & 1) * 2 + 0] = *(uint32_t*)&p01;
        az[nt >> 1][(nt & 1) * 2 + 1] = *(uint32_t*)&p23;
    }

    // ---- stage 2 ----
    float d[8][4];
#pragma unroll
    for (int nt = 0; nt < 8; nt++)
#pragma unroll
        for (int q = 0; q < 4; q++) d[nt][q] = 0.f;
#pragma unroll
    for (int kt = 0; kt < 8; kt++) {
#pragma unroll
        for (int nt = 0; nt < 8; nt++) {
            uint32_t b[2];
            ldmx2(smem_u32(&sW2[(nt * 8 + brow) * STW2 + kt * 16 + bcolbase]), b[0], b[1]);
            mma16816(d[nt], az[kt], b);
        }
    }

    // ---- epilogue 2: + b2 + residual -> h, xcat ----
    int r0 = n0 + m0 + (lane >> 2);
    int r1 = r0 + 8;
    int xoff = (layer + 1) * 64;
#pragma unroll
    for (int nt = 0; nt < 8; nt++) {
        int o0 = nt * 8 + ob;
        float bb0 = __ldg(&b2[o0]);
        float bb1 = __ldg(&b2[o0 + 1]);
        if (r0 < NN) {
            float2 hv = *(float2*)&g_h[r0 * 64 + o0];
            float2 nh;
            nh.x = hv.x + d[nt][0] + bb0;
            nh.y = hv.y + d[nt][1] + bb1;
            *(float2*)&g_h[r0 * 64 + o0] = nh;
            *(float2*)&g_xcat[r0 * 256 + xoff + o0] = nh;
        }
        if (r1 < NN) {
            float2 hv = *(float2*)&g_h[r1 * 64 + o0];
            float2 nh;
            nh.x = hv.x + d[nt][2] + bb0;
            nh.y = hv.y + d[nt][3] + bb1;
            *(float2*)&g_h[r1 * 64 + o0] = nh;
            *(float2*)&g_xcat[r1 * 256 + xoff + o0] = nh;
        }
    }
}
#define MMA_SMEM (256 * 4 + (128 * STA + 128 * STA + 64 * STW2) * 2)

// ---------------- fused pooling + readout MLP --------------------------------
__global__ void k_poolread(const float* __restrict__ W1, const float* __restrict__ b1,
                           const float* __restrict__ W2, const float* __restrict__ b2,
                           const float* __restrict__ Wo, const float* __restrict__ bo,
                           float* __restrict__ out) {
    __shared__ float p[512];
    __shared__ float q1[128];
    __shared__ float q2[64];
    int g = blockIdx.x;
    int tid = threadIdx.x;   // 256
    int beg = g_gstart[g], end = g_gstart[g + 1];
    float sum = 0.f, mx = -INFINITY;
    for (int n = beg; n < end; n++) {
        float v = g_xcat[n * 256 + tid];
        sum += v;
        mx = fmaxf(mx, v);
    }
    float c = (float)(end - beg);
    p[tid] = sum / fmaxf(c, 1.f);
    p[256 + tid] = (end > beg) ? mx : 0.f;
    __syncthreads();
    if (tid < 128) {
        float a = b1[tid];
        for (int k = 0; k < 512; k++) a += p[k] * W1[k * 128 + tid];
        q1[tid] = fmaxf(a, 0.f);
    }
    __syncthreads();
    if (tid < 64) {
        float a = b2[tid];
        for (int k = 0; k < 128; k++) a += q1[k] * W2[k * 64 + tid];
        q2[tid] = fmaxf(a, 0.f);
    }
    __syncthreads();
    if (tid < 32) {
        float s = q2[tid] * Wo[tid] + q2[tid + 32] * Wo[tid + 32];
#pragma unroll
        for (int off = 16; off > 0; off >>= 1) s += __shfl_xor_sync(0xffffffffu, s, off);
        if (tid == 0) out[g] = s + bo[0];
    }
}

// ---------------- launch -----------------------------------------------------
extern "C" void kernel_launch(void* const* d_in, const int* in_sizes, int n_in,
                              void* d_out, int out_size) {
    const float* x        = (const float*)d_in[0];
    const int*   ei       = (const int*)d_in[1];
    const int*   batch    = (const int*)d_in[2];
    const float* conv1_W  = (const float*)d_in[3];
    const float* conv1_b  = (const float*)d_in[4];
    const float* bn1_g    = (const float*)d_in[5];
    const float* bn1_b    = (const float*)d_in[6];
    const float* ln_g     = (const float*)d_in[7];
    const float* ln_b     = (const float*)d_in[8];
    const float* prelu_a  = (const float*)d_in[9];
    const float* gen_t    = (const float*)d_in[10];
    const float* mlp_W1   = (const float*)d_in[11];
    const float* mlp_b1   = (const float*)d_in[12];
    const float* mlp_bn_g = (const float*)d_in[13];
    const float* mlp_bn_b = (const float*)d_in[14];
    const float* mlp_W2   = (const float*)d_in[15];
    const float* mlp_b2   = (const float*)d_in[16];
    const float* lin1_W   = (const float*)d_in[17];
    const float* lin1_b   = (const float*)d_in[18];
    const float* lin2_W   = (const float*)d_in[19];
    const float* lin2_b   = (const float*)d_in[20];
    const float* out_W    = (const float*)d_in[21];
    const float* out_b    = (const float*)d_in[22];
    float* out = (float*)d_out;

    const int* src = ei;
    const int* dst = ei + EE;

    static int smem_set = 0;
    if (!smem_set) {
        cudaFuncSetAttribute(k_mma, cudaFuncAttributeMaxDynamicSharedMemorySize, MMA_SMEM);
        smem_set = 1;
    }

    k_init<<<NBLK, 256>>>();
    k_hist<<<(EE + 255) / 256, 256>>>(dst);
    k_part<<<NBLK, 256>>>();
    k_scan2<<<1, 256>>>();
    k_scan3<<<NBLK, 256>>>();
    k_scatter<<<(EE + 255) / 256, 256>>>(src, dst);
    k_gstart<<<NBLK, 256>>>(batch);
    k_wprep<<<192, 256>>>(mlp_W1, mlp_W2);
    k_hx<<<(NN * 32 + 255) / 256, 256>>>(x, conv1_W);
    k_gcn<<<(NN + 7) / 8, 256>>>(conv1_b, bn1_g, bn1_b);

    for (int i = 0; i < 3; i++) {
        k_ln<<<(NN + 7) / 8, 256>>>(ln_g + i * 64, ln_b + i * 64, prelu_a + i * 64);
        k_gen<<<(NN + 7) / 8, 256>>>(gen_t, i);
        k_mma<<<(NN + 127) / 128, 256, MMA_SMEM>>>(mlp_b1 + i * 128, mlp_bn_g + i * 128,
                                                   mlp_bn_b + i * 128, mlp_b2 + i * 64, i);
    }

    k_poolread<<<GG, 256>>>(lin1_W, lin1_b, lin2_W, lin2_b, out_W, out_b, out);
}